// round 15
// baseline (speedup 1.0000x reference)
#include <cuda_runtime.h>
#include <cuda_fp16.h>
#include <cstdint>

// Problem constants
#define BB   2
#define TT   2048
#define DD   1024
#define HH   16
#define DHH  64
#define MM   (BB*TT)          // 4096
#define ATT_SCALE 0.125f      // DH^-0.5
#define LOG2E_F 1.4426950408889634f

// ---------------------------------------------------------------------------
// Scratch (allocation-free: __device__ globals), all fp16
// ---------------------------------------------------------------------------
__device__ __align__(256) __half g_Q[BB*HH*TT*DHH];   // [b,h,t,dh]
__device__ __align__(256) __half g_K[BB*HH*TT*DHH];
__device__ __align__(256) __half g_V[BB*HH*TT*DHH];
__device__ __align__(256) __half g_O[MM*DD];          // [b,t,h*64+dh]
__device__ __align__(256) __half g_RIN[3*MM*DD];      // fp16 query,key,value
__device__ __align__(256) __half g_RW[4*DD*DD];       // fp16 Wq,Wk,Wv,Wo
__device__ int   g_len[BB];

// ---------------------------------------------------------------------------
// Helpers
// ---------------------------------------------------------------------------
__device__ __forceinline__ float exp2_(float x) {
    float r;
    asm("ex2.approx.ftz.f32 %0, %1;" : "=f"(r) : "f"(x));
    return r;
}
__device__ __forceinline__ uint32_t packh2(float a, float b) {
    __half2 h = __floats2half2_rn(a, b);
    return *reinterpret_cast<uint32_t*>(&h);
}
__device__ __forceinline__ uint32_t ex2h2(uint32_t x) {
    uint32_t r;
    asm("ex2.approx.f16x2 %0, %1;" : "=r"(r) : "r"(x));
    return r;
}
__device__ __forceinline__ void mma16n8k16(float c[4], const uint32_t a[4], const uint32_t b[2]) {
    asm volatile("mma.sync.aligned.m16n8k16.row.col.f32.f16.f16.f32 "
        "{%0,%1,%2,%3}, {%4,%5,%6,%7}, {%8,%9}, {%0,%1,%2,%3};\n"
        : "+f"(c[0]), "+f"(c[1]), "+f"(c[2]), "+f"(c[3])
        : "r"(a[0]), "r"(a[1]), "r"(a[2]), "r"(a[3]), "r"(b[0]), "r"(b[1]));
}
__device__ __forceinline__ void cp16(void* s, const void* g) {
    uint32_t sa = (uint32_t)__cvta_generic_to_shared(s);
    asm volatile("cp.async.cg.shared.global [%0], [%1], 16;\n" :: "r"(sa), "l"(g));
}
__device__ __forceinline__ void ldsm4(uint32_t addr, uint32_t r[4]) {
    asm volatile("ldmatrix.sync.aligned.m8n8.x4.shared.b16 {%0,%1,%2,%3}, [%4];"
        : "=r"(r[0]), "=r"(r[1]), "=r"(r[2]), "=r"(r[3]) : "r"(addr));
}
__device__ __forceinline__ void ldsm4t(uint32_t addr, uint32_t r[4]) {
    asm volatile("ldmatrix.sync.aligned.m8n8.x4.trans.shared.b16 {%0,%1,%2,%3}, [%4];"
        : "=r"(r[0]), "=r"(r[1]), "=r"(r[2]), "=r"(r[3]) : "r"(addr));
}

// ---------------------------------------------------------------------------
// lens kernel (padding length per batch)
// ---------------------------------------------------------------------------
__global__ void lens_kernel(const unsigned char* __restrict__ kpm) {
    __shared__ int sred[256];
    const int b = blockIdx.x;
    const bool is_u8 = (kpm[TT - 1] != 0);
    int cnt = 0;
    if (is_u8) {
        const unsigned char* row = kpm + (size_t)b * TT;
        for (int t = threadIdx.x; t < TT; t += 256) cnt += (row[t] == 0);
    } else {
        const int* row = reinterpret_cast<const int*>(kpm) + (size_t)b * TT;
        for (int t = threadIdx.x; t < TT; t += 256) cnt += (row[t] == 0);
    }
    sred[threadIdx.x] = cnt;
    __syncthreads();
    for (int s = 128; s > 0; s >>= 1) {
        if (threadIdx.x < s) sred[threadIdx.x] += sred[threadIdx.x + s];
        __syncthreads();
    }
    if (threadIdx.x == 0) g_len[b] = sred[0];
}

// ---------------------------------------------------------------------------
// Convert inputs + weights to fp16 (RN). y=0..2 inputs, y=3..6 weights.
// ---------------------------------------------------------------------------
__global__ void __launch_bounds__(256) convert_kernel(
    const float* __restrict__ q, const float* __restrict__ k, const float* __restrict__ v,
    const float* __restrict__ wq, const float* __restrict__ wk,
    const float* __restrict__ wv, const float* __restrict__ wo)
{
    const int y = blockIdx.y;
    const float* src; __half* dst; int n4;
    if (y < 3) {
        src = (y == 0) ? q : (y == 1) ? k : v;
        dst = g_RIN + (size_t)y * (MM * DD);
        n4 = (MM * DD) / 4;
    } else {
        src = (y == 3) ? wq : (y == 4) ? wk : (y == 5) ? wv : wo;
        dst = g_RW + (size_t)(y - 3) * (DD * DD);
        n4 = (DD * DD) / 4;
    }
    const int i = blockIdx.x * 256 + threadIdx.x;
    if (i >= n4) return;
    float4 x = reinterpret_cast<const float4*>(src)[i];
    uint2 o;
    o.x = packh2(x.x, x.y);
    o.y = packh2(x.z, x.w);
    reinterpret_cast<uint2*>(dst)[i] = o;
}

// ---------------------------------------------------------------------------
// FP16 GEMM, 3-stage cp.async ring: 128-thread CTAs (3 CTAs/SM), 128x128 tile,
// BK=32 (2 k16 steps), 2x2 warps of 64x64, LDSM operand loads.
// ---------------------------------------------------------------------------
#define PBM 128
#define PBN 128
#define PBK 32
#define PPDH 40
#define PNKT (DD / PBK)              // 32
#define PASZH (PBM * PPDH)           // 5120 halves per stage per matrix
#define GST 3
#define PSMEM (GST * 2 * PASZH * 2)  // 61,440 B

template<int MODE>   // 0: fp16 head-major out; 1: fp32 row-major out
__device__ __forceinline__ void gemm_body(const __half* __restrict__ A,
                                          const __half* __restrict__ W,
                                          void* __restrict__ outp)
{
    extern __shared__ __half smh[];

    const int tid  = threadIdx.x;
    const int lane = tid & 31, warp = tid >> 5;
    const int wm = warp >> 1, wn = warp & 1;
    const int bm = blockIdx.y * PBM, bn = blockIdx.x * PBN;
    const int lq = lane >> 2, lr = lane & 3;
    const int sub = lane >> 3, l7 = lane & 7;

    float acc[4][8][4];
#pragma unroll
    for (int mt = 0; mt < 4; mt++)
#pragma unroll
        for (int nt = 0; nt < 8; nt++)
#pragma unroll
            for (int j = 0; j < 4; j++) acc[mt][nt][j] = 0.f;

    const __half* Abase = A + (size_t)bm * DD;
    const __half* Wbase = W + (size_t)bn * DD;

    auto load_tile = [&](int kt, int st) {
        const int k0 = kt * PBK;
        __half* Ad = smh + st * 2 * PASZH;
        __half* Bd = Ad + PASZH;
#pragma unroll
        for (int i = 0; i < 4; i++) {
            const int idx = tid + i * 128;
            const int r = idx >> 2, j = idx & 3;
            cp16(&Ad[r * PPDH + j * 8], Abase + (size_t)r * DD + k0 + j * 8);
        }
#pragma unroll
        for (int i = 0; i < 4; i++) {
            const int idx = tid + i * 128;
            const int r = idx >> 2, j = idx & 3;
            cp16(&Bd[r * PPDH + j * 8], Wbase + (size_t)r * DD + k0 + j * 8);
        }
        asm volatile("cp.async.commit_group;\n");
    };

    load_tile(0, 0);
    load_tile(1, 1);

    int st = 0;
    for (int kt = 0; kt < PNKT; kt++) {
        if (kt + 1 < PNKT) asm volatile("cp.async.wait_group 1;\n");
        else               asm volatile("cp.async.wait_group 0;\n");
        __syncthreads();
        if (kt + 2 < PNKT) load_tile(kt + 2, (st + 2) % GST);

        const uint32_t Abu = (uint32_t)__cvta_generic_to_shared(smh + st * 2 * PASZH);
        const uint32_t Bbu = Abu + PASZH * 2;

#pragma unroll
        for (int ks = 0; ks < 2; ks++) {
            const int c = ks * 16;
            uint32_t af[4][4], bfq[4][4];
            {
                const int row_off = (sub & 1) * 8 + l7;
                const int col = c + (sub >> 1) * 8;
#pragma unroll
                for (int mt = 0; mt < 4; mt++) {
                    const int row = wm * 64 + mt * 16 + row_off;
                    ldsm4(Abu + (uint32_t)(row * PPDH + col) * 2, af[mt]);
                }
            }
            {
                const int row_off = (sub >> 1) * 8 + l7;
                const int col = c + (sub & 1) * 8;
#pragma unroll
                for (int ntp = 0; ntp < 4; ntp++) {
                    const int row = wn * 64 + ntp * 16 + row_off;
                    ldsm4(Bbu + (uint32_t)(row * PPDH + col) * 2, bfq[ntp]);
                }
            }
#pragma unroll
            for (int ntp = 0; ntp < 4; ntp++) {
                uint32_t b0[2] = {bfq[ntp][0], bfq[ntp][1]};
                uint32_t b1[2] = {bfq[ntp][2], bfq[ntp][3]};
#pragma unroll
                for (int mt = 0; mt < 4; mt++) {
                    mma16n8k16(acc[mt][2 * ntp],     af[mt], b0);
                    mma16n8k16(acc[mt][2 * ntp + 1], af[mt], b1);
                }
            }
        }
        st = (st + 1) % GST;
    }

    // epilogue
#pragma unroll
    for (int mt = 0; mt < 4; mt++) {
        const int gm = bm + wm * 64 + mt * 16 + lq;
#pragma unroll
        for (int nt = 0; nt < 8; nt++) {
            const int gn = bn + wn * 64 + nt * 8 + (lr << 1);
            if (MODE == 0) {
                __half* out = (__half*)outp;
                const int h = gn >> 6, dh = gn & 63;
                const int b0 = gm >> 11, t0 = gm & (TT - 1);
                *reinterpret_cast<uint32_t*>(
                    &out[(((size_t)b0 * HH + h) * TT + t0) * DHH + dh]) =
                    packh2(acc[mt][nt][0], acc[mt][nt][1]);
                const int gm1 = gm + 8;
                const int b1 = gm1 >> 11, t1 = gm1 & (TT - 1);
                *reinterpret_cast<uint32_t*>(
                    &out[(((size_t)b1 * HH + h) * TT + t1) * DHH + dh]) =
                    packh2(acc[mt][nt][2], acc[mt][nt][3]);
            } else {
                float* out = (float*)outp;
                *reinterpret_cast<float2*>(&out[(size_t)gm * DD + gn]) =
                    make_float2(acc[mt][nt][0], acc[mt][nt][1]);
                *reinterpret_cast<float2*>(&out[(size_t)(gm + 8) * DD + gn]) =
                    make_float2(acc[mt][nt][2], acc[mt][nt][3]);
            }
        }
    }
}

__global__ void __launch_bounds__(128, 3)
proj_qkv_kernel()
{
    const int z = blockIdx.z;
    const __half* A = g_RIN + (size_t)z * (MM * DD);
    const __half* W = g_RW + (size_t)z * (DD * DD);
    __half* out = (z == 0) ? g_Q : (z == 1) ? g_K : g_V;
    gemm_body<0>(A, W, out);
}

__global__ void __launch_bounds__(128, 3)
proj_o_kernel(float* __restrict__ out)
{
    gemm_body<1>(g_O, g_RW + 3 * (size_t)(DD * DD), out);
}

// ---------------------------------------------------------------------------
// FP16 flash attention (unchanged from R14): 64 q-rows/CTA, 4 CTAs/SM,
// f16x2 exp, ones-MMA row sums, LPT.
// ---------------------------------------------------------------------------
#define AKPH 72
#define A_KS_OFF 0
#define A_VS_OFF 9216
#define A_PS_OFF 18432
#define A_SMEM   ((18432 + 4608) * 2)    // 46,080 B

__global__ void __launch_bounds__(128, 4) attn_kernel()
{
    extern __shared__ __half smh[];
    __half* Ps = smh + A_PS_OFF;

    const int qi = gridDim.x - 1 - blockIdx.x;   // LPT: heavy CTAs first
    const int h = blockIdx.y, b = blockIdx.z;
    const int tid = threadIdx.x, warp = tid >> 5, lane = tid & 31;
    const int len = g_len[b];
    const int lq = lane >> 2, lr = lane & 3;
    const int sub = lane >> 3, l7 = lane & 7;

    const size_t base = ((size_t)b * HH + h) * TT * DHH;
    const __half* __restrict__ Qb = g_Q + base;
    const __half* __restrict__ Kb = g_K + base;
    const __half* __restrict__ Vb = g_V + base;

    const uint32_t ps_u = (uint32_t)__cvta_generic_to_shared(Ps);

#pragma unroll
    for (int i = 0; i < 4; i++) {
        const int idx = tid + i * 128;
        const int r = idx >> 3, j = idx & 7;
        *reinterpret_cast<uint4*>(&Ps[r * AKPH + j * 8]) =
            *reinterpret_cast<const uint4*>(&Qb[(size_t)(qi * 64 + r) * DHH + j * 8]);
    }
    __syncthreads();

    uint32_t qf[4][4];
    {
        const int row = warp * 16 + (sub & 1) * 8 + l7;
        const int col_off = (sub >> 1) * 8;
#pragma unroll
        for (int ks = 0; ks < 4; ks++)
            ldsm4(ps_u + (uint32_t)(row * AKPH + ks * 16 + col_off) * 2, qf[ks]);
    }
    __syncthreads();

    float oacc[8][4];
#pragma unroll
    for (int nt = 0; nt < 8; nt++)
#pragma unroll
        for (int j = 0; j < 4; j++) oacc[nt][j] = 0.f;

    float lacc[4] = {0.f, 0.f, 0.f, 0.f};
    float mrowA = -1e30f, mrowB = -1e30f;

    const int ktend = min(qi + 1, (len + 63) >> 6);
    const float SE = ATT_SCALE * LOG2E_F;
    const uint32_t ones2[2] = {0x3C003C00u, 0x3C003C00u};

    auto load_kv = [&](int kt, int bufi) {
        const __half* Kp = Kb + (size_t)(kt * 64) * DHH;
        const __half* Vp = Vb + (size_t)(kt * 64) * DHH;
        __half* Kd = smh + A_KS_OFF + bufi * 64 * AKPH;
        __half* Vd = smh + A_VS_OFF + bufi * 64 * AKPH;
#pragma unroll
        for (int i = 0; i < 4; i++) {
            const int idx = tid + i * 128;
            const int r = idx >> 3, j = idx & 7;
            cp16(Kd + r * AKPH + j * 8, Kp + (size_t)r * DHH + j * 8);
            cp16(Vd + r * AKPH + j * 8, Vp + (size_t)r * DHH + j * 8);
        }
        asm volatile("cp.async.commit_group;\n");
    };

    load_kv(0, 0);

    const int prow = warp * 16 + lq;

    for (int kt = 0; kt < ktend; kt++) {
        const int buf = kt & 1;
        asm volatile("cp.async.wait_group 0;\n");
        __syncthreads();
        if (kt + 1 < ktend) load_kv(kt + 1, buf ^ 1);

        const uint32_t kt_u = (uint32_t)__cvta_generic_to_shared(smh + A_KS_OFF + buf * 64 * AKPH);
        const uint32_t vt_u = (uint32_t)__cvta_generic_to_shared(smh + A_VS_OFF + buf * 64 * AKPH);

        // ---- S = Q K^T ----
        float s[8][4];
#pragma unroll
        for (int nt = 0; nt < 8; nt++)
#pragma unroll
            for (int j = 0; j < 4; j++) s[nt][j] = 0.f;
        {
            const int row_off = (sub >> 1) * 8 + l7;
            const int col_off = (sub & 1) * 8;
#pragma unroll
            for (int ks = 0; ks < 4; ks++) {
                const int c = ks * 16 + col_off;
#pragma unroll
                for (int ntp = 0; ntp < 4; ntp++) {
                    uint32_t kf[4];
                    ldsm4(kt_u + (uint32_t)((ntp * 16 + row_off) * AKPH + c) * 2, kf);
                    uint32_t b0[2] = {kf[0], kf[1]};
                    uint32_t b1[2] = {kf[2], kf[3]};
                    mma16n8k16(s[2 * ntp],     qf[ks], b0);
                    mma16n8k16(s[2 * ntp + 1], qf[ks], b1);
                }
            }
        }

        // ---- scale + mask ----
        const bool need_mask = (kt == qi) || (((kt + 1) << 6) > len);
        if (need_mask) {
            const int qg0 = qi * 64 + warp * 16 + lq;
#pragma unroll
            for (int nt = 0; nt < 8; nt++) {
#pragma unroll
                for (int j = 0; j < 4; j++) {
                    float v = s[nt][j] * SE;
                    const int kg = kt * 64 + nt * 8 + (lr << 1) + (j & 1);
                    const int qg = qg0 + ((j & 2) << 2);
                    if (kg > qg || kg >= len) v = -1e30f;
                    s[nt][j] = v;
                }
            }
        } else {
#pragma unroll
            for (int nt = 0; nt < 8; nt++)
#pragma unroll
                for (int j = 0; j < 4; j++) s[nt][j] *= SE;
        }

        // ---- online softmax: max reduce, f16x2 exp, store P ----
        {
            float tA = -1e30f, tB = -1e30f;
#pragma unroll
            for (int nt = 0; nt < 8; nt++) {
                tA = fmaxf(tA, fmaxf(s[nt][0], s[nt][1]));
                tB = fmaxf(tB, fmaxf(s[nt][2], s[nt][3]));
            }
            tA = fmaxf(tA, __shfl_xor_sync(0xffffffffu, tA, 1));
            tA = fmaxf(tA, __shfl_xor_sync(0xffffffffu, tA, 2));
            tB = fmaxf(tB, __shfl_xor_sync(0xffffffffu, tB, 1));
            tB = fmaxf(tB, __shfl_xor_sync(0xffffffffu, tB, 2));
            const float mA = fmaxf(mrowA, tA), mB = fmaxf(mrowB, tB);
            const float aA = exp2_(mrowA - mA), aB = exp2_(mrowB - mB);

#pragma unroll
            for (int nt = 0; nt < 8; nt++) {
                const uint32_t x0 = packh2(s[nt][0] - mA, s[nt][1] - mA);
                const uint32_t x1 = packh2(s[nt][2] - mB, s[nt][3] - mB);
                const int c = nt * 8 + (lr << 1);
                *reinterpret_cast<uint32_t*>(&Ps[prow * AKPH + c]) = ex2h2(x0);
                *reinterpret_cast<uint32_t*>(&Ps[(prow + 8) * AKPH + c]) = ex2h2(x1);
            }
            mrowA = mA;
            mrowB = mB;
            lacc[0] *= aA; lacc[1] *= aA;
            lacc[2] *= aB; lacc[3] *= aB;
#pragma unroll
            for (int nt = 0; nt < 8; nt++) {
                oacc[nt][0] *= aA; oacc[nt][1] *= aA;
                oacc[nt][2] *= aB; oacc[nt][3] *= aB;
            }
        }
        __syncwarp();

        // ---- O += P V ; l += P @ ones ----
        {
            const int prow_off = warp * 16 + (sub & 1) * 8 + l7;
            const int pcol_off = (sub >> 1) * 8;
#pragma unroll
            for (int ks = 0; ks < 4; ks++) {
                uint32_t pa[4];
                ldsm4(ps_u + (uint32_t)(prow_off * AKPH + ks * 16 + pcol_off) * 2, pa);
                mma16n8k16(lacc, pa, ones2);
#pragma unroll
                for (int ntp = 0; ntp < 4; ntp++) {
                    const int row = ks * 16 + ((lane >> 3) & 1) * 8 + (lane & 7);
                    const int col = ntp * 16 + ((lane >> 4) << 3);
                    uint32_t vf[4];
                    ldsm4t(vt_u + (uint32_t)(row * AKPH + col) * 2, vf);
                    uint32_t b0[2] = {vf[0], vf[1]}, b1[2] = {vf[2], vf[3]};
                    mma16n8k16(oacc[2 * ntp],     pa, b0);
                    mma16n8k16(oacc[2 * ntp + 1], pa, b1);
                }
            }
        }
        __syncwarp();
    }

    // ---- finalize: fp16 O in [b,t,h*64+dh] ----
    __half* __restrict__ Ob = g_O + ((size_t)b * TT) * DD + h * DHH;
    {
        const float invA = 1.f / lacc[0], invB = 1.f / lacc[2];
        const int q0 = qi * 64 + warp * 16 + lq;
#pragma unroll
        for (int nt = 0; nt < 8; nt++) {
            const int dh = nt * 8 + (lr << 1);
            *reinterpret_cast<uint32_t*>(&Ob[(size_t)q0 * DD + dh]) =
                packh2(oacc[nt][0] * invA, oacc[nt][1] * invA);
            *reinterpret_cast<uint32_t*>(&Ob[(size_t)(q0 + 8) * DD + dh]) =
                packh2(oacc[nt][2] * invB, oacc[nt][3] * invB);
        }
    }
}

// ---------------------------------------------------------------------------
// Launch
// ---------------------------------------------------------------------------
extern "C" void kernel_launch(void* const* d_in, const int* in_sizes, int n_in,
                              void* d_out, int out_size)
{
    const float* big[4] = {nullptr, nullptr, nullptr, nullptr};
    const float* w[4]   = {nullptr, nullptr, nullptr, nullptr};
    const unsigned char* kpm = nullptr;
    int nbig = 0, nw = 0;
    for (int i = 0; i < n_in; i++) {
        if (in_sizes[i] == TT * TT && nbig < 4) big[nbig++] = (const float*)d_in[i];
        else if (in_sizes[i] == DD * DD && nw < 4) w[nw++] = (const float*)d_in[i];
        else if (in_sizes[i] == BB * TT) kpm = (const unsigned char*)d_in[i];
    }
    const float* query = big[0];
    const float* key_t = big[1];
    const float* value = big[2];
    const float* Wq = w[0];
    const float* Wk = w[1];
    const float* Wv = w[2];
    const float* Wo = w[3];
    float* out = (float*)d_out;

    static bool attr_set = false;
    if (!attr_set) {
        cudaFuncSetAttribute(proj_qkv_kernel, cudaFuncAttributeMaxDynamicSharedMemorySize, PSMEM);
        cudaFuncSetAttribute(proj_o_kernel, cudaFuncAttributeMaxDynamicSharedMemorySize, PSMEM);
        cudaFuncSetAttribute(attn_kernel, cudaFuncAttributeMaxDynamicSharedMemorySize, A_SMEM);
        attr_set = true;
    }

    lens_kernel<<<BB, 256>>>(kpm);
    convert_kernel<<<dim3((MM * DD) / 4 / 256, 7), 256>>>(query, key_t, value, Wq, Wk, Wv, Wo);
    proj_qkv_kernel<<<dim3(DD / PBN, MM / PBM, 3), 128, PSMEM>>>();
    attn_kernel<<<dim3(TT / 64, HH, BB), 128, A_SMEM>>>();
    proj_o_kernel<<<dim3(DD / PBN, MM / PBM, 1), 128, PSMEM>>>(out);
}

// round 16
// speedup vs baseline: 1.0846x; 1.0846x over previous
#include <cuda_runtime.h>
#include <cuda_fp16.h>
#include <cstdint>

// Problem constants
#define BB   2
#define TT   2048
#define DD   1024
#define HH   16
#define DHH  64
#define MM   (BB*TT)          // 4096
#define ATT_SCALE 0.125f      // DH^-0.5
#define LOG2E_F 1.4426950408889634f

// ---------------------------------------------------------------------------
// Scratch (allocation-free: __device__ globals), all fp16
// ---------------------------------------------------------------------------
__device__ __align__(256) __half g_Q[BB*HH*TT*DHH];   // [b,h,t,dh]
__device__ __align__(256) __half g_K[BB*HH*TT*DHH];
__device__ __align__(256) __half g_V[BB*HH*TT*DHH];
__device__ __align__(256) __half g_O[MM*DD];          // [b,t,h*64+dh]
__device__ __align__(256) __half g_RW[4*DD*DD];       // fp16 Wq,Wk,Wv,Wo
__device__ int   g_len[BB];

// ---------------------------------------------------------------------------
// Helpers
// ---------------------------------------------------------------------------
__device__ __forceinline__ float exp2_(float x) {
    float r;
    asm("ex2.approx.ftz.f32 %0, %1;" : "=f"(r) : "f"(x));
    return r;
}
__device__ __forceinline__ uint32_t packh2(float a, float b) {
    __half2 h = __floats2half2_rn(a, b);
    return *reinterpret_cast<uint32_t*>(&h);
}
__device__ __forceinline__ uint32_t ex2h2(uint32_t x) {
    uint32_t r;
    asm("ex2.approx.f16x2 %0, %1;" : "=r"(r) : "r"(x));
    return r;
}
__device__ __forceinline__ void mma16n8k16(float c[4], const uint32_t a[4], const uint32_t b[2]) {
    asm volatile("mma.sync.aligned.m16n8k16.row.col.f32.f16.f16.f32 "
        "{%0,%1,%2,%3}, {%4,%5,%6,%7}, {%8,%9}, {%0,%1,%2,%3};\n"
        : "+f"(c[0]), "+f"(c[1]), "+f"(c[2]), "+f"(c[3])
        : "r"(a[0]), "r"(a[1]), "r"(a[2]), "r"(a[3]), "r"(b[0]), "r"(b[1]));
}
__device__ __forceinline__ void cp16(void* s, const void* g) {
    uint32_t sa = (uint32_t)__cvta_generic_to_shared(s);
    asm volatile("cp.async.cg.shared.global [%0], [%1], 16;\n" :: "r"(sa), "l"(g));
}
__device__ __forceinline__ void ldsm4(uint32_t addr, uint32_t r[4]) {
    asm volatile("ldmatrix.sync.aligned.m8n8.x4.shared.b16 {%0,%1,%2,%3}, [%4];"
        : "=r"(r[0]), "=r"(r[1]), "=r"(r[2]), "=r"(r[3]) : "r"(addr));
}
__device__ __forceinline__ void ldsm4t(uint32_t addr, uint32_t r[4]) {
    asm volatile("ldmatrix.sync.aligned.m8n8.x4.trans.shared.b16 {%0,%1,%2,%3}, [%4];"
        : "=r"(r[0]), "=r"(r[1]), "=r"(r[2]), "=r"(r[3]) : "r"(addr));
}

// ---------------------------------------------------------------------------
// lens kernel (padding length per batch)
// ---------------------------------------------------------------------------
__global__ void lens_kernel(const unsigned char* __restrict__ kpm) {
    __shared__ int sred[256];
    const int b = blockIdx.x;
    const bool is_u8 = (kpm[TT - 1] != 0);
    int cnt = 0;
    if (is_u8) {
        const unsigned char* row = kpm + (size_t)b * TT;
        for (int t = threadIdx.x; t < TT; t += 256) cnt += (row[t] == 0);
    } else {
        const int* row = reinterpret_cast<const int*>(kpm) + (size_t)b * TT;
        for (int t = threadIdx.x; t < TT; t += 256) cnt += (row[t] == 0);
    }
    sred[threadIdx.x] = cnt;
    __syncthreads();
    for (int s = 128; s > 0; s >>= 1) {
        if (threadIdx.x < s) sred[threadIdx.x] += sred[threadIdx.x + s];
        __syncthreads();
    }
    if (threadIdx.x == 0) g_len[b] = sred[0];
}

// ---------------------------------------------------------------------------
// Convert WEIGHTS ONLY to fp16 (inputs converted inside the QKV GEMM).
// ---------------------------------------------------------------------------
__global__ void __launch_bounds__(256) round_kernel(
    const float* __restrict__ wq, const float* __restrict__ wk,
    const float* __restrict__ wv, const float* __restrict__ wo)
{
    const int y = blockIdx.y;
    const float* src = (y == 0) ? wq : (y == 1) ? wk : (y == 2) ? wv : wo;
    __half* dst = g_RW + (size_t)y * (DD * DD);
    const int i = blockIdx.x * 256 + threadIdx.x;
    float4 x = reinterpret_cast<const float4*>(src)[i];
    uint2 o;
    o.x = packh2(x.x, x.y);
    o.y = packh2(x.z, x.w);
    reinterpret_cast<uint2*>(dst)[i] = o;
}

// ---------------------------------------------------------------------------
// Shared GEMM tile geometry
// ---------------------------------------------------------------------------
#define PBM 128
#define PBN 128
#define PBK 32
#define PPDH 40
#define PNKT (DD / PBK)              // 32
#define PASZH (PBM * PPDH)           // 5120 halves
#define PSMEM_QKV (4 * PASZH * 2)    // 40,960 B  (A 2-buf + B 2-buf)
#define GST 3
#define PSMEM_O (GST * 2 * PASZH * 2) // 61,440 B (3-stage A+B ring)

// ---------------------------------------------------------------------------
// QKV GEMM (R14): A fp32 in gmem, converted to fp16 during staging
// (LDG.128 -> cvt -> STS, register-double-buffered); B fp16 via cp.async.
// ---------------------------------------------------------------------------
__global__ void __launch_bounds__(128, 2)
proj_qkv_kernel(const float* __restrict__ qin, const float* __restrict__ kin,
                const float* __restrict__ vin)
{
    extern __shared__ __half smh[];
    __half* As = smh;
    __half* Bs = smh + 2 * PASZH;

    const int z = blockIdx.z;
    const float* A = (z == 0) ? qin : (z == 1) ? kin : vin;
    const __half* W = g_RW + (size_t)z * (DD * DD);
    __half* out = (z == 0) ? g_Q : (z == 1) ? g_K : g_V;

    const int tid  = threadIdx.x;
    const int lane = tid & 31, warp = tid >> 5;
    const int wm = warp >> 1, wn = warp & 1;
    const int bm = blockIdx.y * PBM, bn = blockIdx.x * PBN;
    const int lq = lane >> 2, lr = lane & 3;
    const int sub = lane >> 3, l7 = lane & 7;

    float acc[4][8][4];
#pragma unroll
    for (int mt = 0; mt < 4; mt++)
#pragma unroll
        for (int nt = 0; nt < 8; nt++)
#pragma unroll
            for (int j = 0; j < 4; j++) acc[mt][nt][j] = 0.f;

    const float* Abase = A + (size_t)bm * DD;
    const __half* Wbase = W + (size_t)bn * DD;

    const int aj = tid & 7;
    float4 areg[8];

    auto ldgA = [&](int kt) {
        const int k0 = kt * PBK;
#pragma unroll
        for (int i = 0; i < 8; i++) {
            const int r = (tid >> 3) + i * 16;
            areg[i] = *reinterpret_cast<const float4*>(Abase + (size_t)r * DD + k0 + aj * 4);
        }
    };
    auto stsA = [&](int buf) {
#pragma unroll
        for (int i = 0; i < 8; i++) {
            const int r = (tid >> 3) + i * 16;
            uint2 o;
            o.x = packh2(areg[i].x, areg[i].y);
            o.y = packh2(areg[i].z, areg[i].w);
            *reinterpret_cast<uint2*>(&As[buf * PASZH + r * PPDH + aj * 4]) = o;
        }
    };
    auto cpB = [&](int kt, int buf) {
        const int k0 = kt * PBK;
#pragma unroll
        for (int i = 0; i < 4; i++) {
            const int idx = tid + i * 128;
            const int r = idx >> 2, j = idx & 3;
            cp16(&Bs[buf * PASZH + r * PPDH + j * 8], Wbase + (size_t)r * DD + k0 + j * 8);
        }
        asm volatile("cp.async.commit_group;\n");
    };

    ldgA(0);
    stsA(0);
    cpB(0, 0);
    ldgA(1);

    for (int kt = 0; kt < PNKT; kt++) {
        const int buf = kt & 1;
        asm volatile("cp.async.wait_group 0;\n");
        __syncthreads();

        if (kt + 1 < PNKT) {
            cpB(kt + 1, buf ^ 1);
            stsA(buf ^ 1);
            if (kt + 2 < PNKT) ldgA(kt + 2);
        }

        const uint32_t Abu = (uint32_t)__cvta_generic_to_shared(&As[buf * PASZH]);
        const uint32_t Bbu = (uint32_t)__cvta_generic_to_shared(&Bs[buf * PASZH]);

#pragma unroll
        for (int ks = 0; ks < 2; ks++) {
            const int c = ks * 16;
            uint32_t af[4][4], bfq[4][4];
            {
                const int row_off = (sub & 1) * 8 + l7;
                const int col = c + (sub >> 1) * 8;
#pragma unroll
                for (int mt = 0; mt < 4; mt++) {
                    const int row = wm * 64 + mt * 16 + row_off;
                    ldsm4(Abu + (uint32_t)(row * PPDH + col) * 2, af[mt]);
                }
            }
            {
                const int row_off = (sub >> 1) * 8 + l7;
                const int col = c + (sub & 1) * 8;
#pragma unroll
                for (int ntp = 0; ntp < 4; ntp++) {
                    const int row = wn * 64 + ntp * 16 + row_off;
                    ldsm4(Bbu + (uint32_t)(row * PPDH + col) * 2, bfq[ntp]);
                }
            }
#pragma unroll
            for (int ntp = 0; ntp < 4; ntp++) {
                uint32_t b0[2] = {bfq[ntp][0], bfq[ntp][1]};
                uint32_t b1[2] = {bfq[ntp][2], bfq[ntp][3]};
#pragma unroll
                for (int mt = 0; mt < 4; mt++) {
                    mma16n8k16(acc[mt][2 * ntp],     af[mt], b0);
                    mma16n8k16(acc[mt][2 * ntp + 1], af[mt], b1);
                }
            }
        }
    }

#pragma unroll
    for (int mt = 0; mt < 4; mt++) {
        const int gm = bm + wm * 64 + mt * 16 + lq;
#pragma unroll
        for (int nt = 0; nt < 8; nt++) {
            const int gn = bn + wn * 64 + nt * 8 + (lr << 1);
            const int h = gn >> 6, dh = gn & 63;
            const int b0 = gm >> 11, t0 = gm & (TT - 1);
            *reinterpret_cast<uint32_t*>(
                &out[(((size_t)b0 * HH + h) * TT + t0) * DHH + dh]) =
                packh2(acc[mt][nt][0], acc[mt][nt][1]);
            const int gm1 = gm + 8;
            const int b1 = gm1 >> 11, t1 = gm1 & (TT - 1);
            *reinterpret_cast<uint32_t*>(
                &out[(((size_t)b1 * HH + h) * TT + t1) * DHH + dh]) =
                packh2(acc[mt][nt][2], acc[mt][nt][3]);
        }
    }
}

// ---------------------------------------------------------------------------
// O-projection: fp16 A (g_O) + fp16 B (Wo), 3-stage cp.async ring, 3 CTAs/SM,
// fp32 row-major out.
// ---------------------------------------------------------------------------
__global__ void __launch_bounds__(128, 3)
proj_o_kernel(float* __restrict__ out)
{
    extern __shared__ __half smh[];

    const __half* A = g_O;
    const __half* W = g_RW + 3 * (size_t)(DD * DD);

    const int tid  = threadIdx.x;
    const int lane = tid & 31, warp = tid >> 5;
    const int wm = warp >> 1, wn = warp & 1;
    const int bm = blockIdx.y * PBM, bn = blockIdx.x * PBN;
    const int lq = lane >> 2, lr = lane & 3;
    const int sub = lane >> 3, l7 = lane & 7;

    float acc[4][8][4];
#pragma unroll
    for (int mt = 0; mt < 4; mt++)
#pragma unroll
        for (int nt = 0; nt < 8; nt++)
#pragma unroll
            for (int j = 0; j < 4; j++) acc[mt][nt][j] = 0.f;

    const __half* Abase = A + (size_t)bm * DD;
    const __half* Wbase = W + (size_t)bn * DD;

    auto load_tile = [&](int kt, int st) {
        const int k0 = kt * PBK;
        __half* Ad = smh + st * 2 * PASZH;
        __half* Bd = Ad + PASZH;
#pragma unroll
        for (int i = 0; i < 4; i++) {
            const int idx = tid + i * 128;
            const int r = idx >> 2, j = idx & 3;
            cp16(&Ad[r * PPDH + j * 8], Abase + (size_t)r * DD + k0 + j * 8);
        }
#pragma unroll
        for (int i = 0; i < 4; i++) {
            const int idx = tid + i * 128;
            const int r = idx >> 2, j = idx & 3;
            cp16(&Bd[r * PPDH + j * 8], Wbase + (size_t)r * DD + k0 + j * 8);
        }
        asm volatile("cp.async.commit_group;\n");
    };

    load_tile(0, 0);
    load_tile(1, 1);

    int st = 0;
    for (int kt = 0; kt < PNKT; kt++) {
        if (kt + 1 < PNKT) asm volatile("cp.async.wait_group 1;\n");
        else               asm volatile("cp.async.wait_group 0;\n");
        __syncthreads();
        if (kt + 2 < PNKT) load_tile(kt + 2, (st + 2) % GST);

        const uint32_t Abu = (uint32_t)__cvta_generic_to_shared(smh + st * 2 * PASZH);
        const uint32_t Bbu = Abu + PASZH * 2;

#pragma unroll
        for (int ks = 0; ks < 2; ks++) {
            const int c = ks * 16;
            uint32_t af[4][4], bfq[4][4];
            {
                const int row_off = (sub & 1) * 8 + l7;
                const int col = c + (sub >> 1) * 8;
#pragma unroll
                for (int mt = 0; mt < 4; mt++) {
                    const int row = wm * 64 + mt * 16 + row_off;
                    ldsm4(Abu + (uint32_t)(row * PPDH + col) * 2, af[mt]);
                }
            }
            {
                const int row_off = (sub >> 1) * 8 + l7;
                const int col = c + (sub & 1) * 8;
#pragma unroll
                for (int ntp = 0; ntp < 4; ntp++) {
                    const int row = wn * 64 + ntp * 16 + row_off;
                    ldsm4(Bbu + (uint32_t)(row * PPDH + col) * 2, bfq[ntp]);
                }
            }
#pragma unroll
            for (int ntp = 0; ntp < 4; ntp++) {
                uint32_t b0[2] = {bfq[ntp][0], bfq[ntp][1]};
                uint32_t b1[2] = {bfq[ntp][2], bfq[ntp][3]};
#pragma unroll
                for (int mt = 0; mt < 4; mt++) {
                    mma16n8k16(acc[mt][2 * ntp],     af[mt], b0);
                    mma16n8k16(acc[mt][2 * ntp + 1], af[mt], b1);
                }
            }
        }
        st = (st + 1) % GST;
    }

#pragma unroll
    for (int mt = 0; mt < 4; mt++) {
        const int gm = bm + wm * 64 + mt * 16 + lq;
#pragma unroll
        for (int nt = 0; nt < 8; nt++) {
            const int gn = bn + wn * 64 + nt * 8 + (lr << 1);
            *reinterpret_cast<float2*>(&out[(size_t)gm * DD + gn]) =
                make_float2(acc[mt][nt][0], acc[mt][nt][1]);
            *reinterpret_cast<float2*>(&out[(size_t)(gm + 8) * DD + gn]) =
                make_float2(acc[mt][nt][2], acc[mt][nt][3]);
        }
    }
}

// ---------------------------------------------------------------------------
// FP16 flash attention (R14): 64 q-rows/CTA, 4 CTAs/SM, f16x2 exp,
// ones-MMA row sums, LPT.
// ---------------------------------------------------------------------------
#define AKPH 72
#define A_KS_OFF 0
#define A_VS_OFF 9216
#define A_PS_OFF 18432
#define A_SMEM   ((18432 + 4608) * 2)    // 46,080 B

__global__ void __launch_bounds__(128, 4) attn_kernel()
{
    extern __shared__ __half smh[];
    __half* Ps = smh + A_PS_OFF;

    const int qi = gridDim.x - 1 - blockIdx.x;   // LPT: heavy CTAs first
    const int h = blockIdx.y, b = blockIdx.z;
    const int tid = threadIdx.x, warp = tid >> 5, lane = tid & 31;
    const int len = g_len[b];
    const int lq = lane >> 2, lr = lane & 3;
    const int sub = lane >> 3, l7 = lane & 7;

    const size_t base = ((size_t)b * HH + h) * TT * DHH;
    const __half* __restrict__ Qb = g_Q + base;
    const __half* __restrict__ Kb = g_K + base;
    const __half* __restrict__ Vb = g_V + base;

    const uint32_t ps_u = (uint32_t)__cvta_generic_to_shared(Ps);

#pragma unroll
    for (int i = 0; i < 4; i++) {
        const int idx = tid + i * 128;
        const int r = idx >> 3, j = idx & 7;
        *reinterpret_cast<uint4*>(&Ps[r * AKPH + j * 8]) =
            *reinterpret_cast<const uint4*>(&Qb[(size_t)(qi * 64 + r) * DHH + j * 8]);
    }
    __syncthreads();

    uint32_t qf[4][4];
    {
        const int row = warp * 16 + (sub & 1) * 8 + l7;
        const int col_off = (sub >> 1) * 8;
#pragma unroll
        for (int ks = 0; ks < 4; ks++)
            ldsm4(ps_u + (uint32_t)(row * AKPH + ks * 16 + col_off) * 2, qf[ks]);
    }
    __syncthreads();

    float oacc[8][4];
#pragma unroll
    for (int nt = 0; nt < 8; nt++)
#pragma unroll
        for (int j = 0; j < 4; j++) oacc[nt][j] = 0.f;

    float lacc[4] = {0.f, 0.f, 0.f, 0.f};
    float mrowA = -1e30f, mrowB = -1e30f;

    const int ktend = min(qi + 1, (len + 63) >> 6);
    const float SE = ATT_SCALE * LOG2E_F;
    const uint32_t ones2[2] = {0x3C003C00u, 0x3C003C00u};

    auto load_kv = [&](int kt, int bufi) {
        const __half* Kp = Kb + (size_t)(kt * 64) * DHH;
        const __half* Vp = Vb + (size_t)(kt * 64) * DHH;
        __half* Kd = smh + A_KS_OFF + bufi * 64 * AKPH;
        __half* Vd = smh + A_VS_OFF + bufi * 64 * AKPH;
#pragma unroll
        for (int i = 0; i < 4; i++) {
            const int idx = tid + i * 128;
            const int r = idx >> 3, j = idx & 7;
            cp16(Kd + r * AKPH + j * 8, Kp + (size_t)r * DHH + j * 8);
            cp16(Vd + r * AKPH + j * 8, Vp + (size_t)r * DHH + j * 8);
        }
        asm volatile("cp.async.commit_group;\n");
    };

    load_kv(0, 0);

    const int prow = warp * 16 + lq;

    for (int kt = 0; kt < ktend; kt++) {
        const int buf = kt & 1;
        asm volatile("cp.async.wait_group 0;\n");
        __syncthreads();
        if (kt + 1 < ktend) load_kv(kt + 1, buf ^ 1);

        const uint32_t kt_u = (uint32_t)__cvta_generic_to_shared(smh + A_KS_OFF + buf * 64 * AKPH);
        const uint32_t vt_u = (uint32_t)__cvta_generic_to_shared(smh + A_VS_OFF + buf * 64 * AKPH);

        // ---- S = Q K^T ----
        float s[8][4];
#pragma unroll
        for (int nt = 0; nt < 8; nt++)
#pragma unroll
            for (int j = 0; j < 4; j++) s[nt][j] = 0.f;
        {
            const int row_off = (sub >> 1) * 8 + l7;
            const int col_off = (sub & 1) * 8;
#pragma unroll
            for (int ks = 0; ks < 4; ks++) {
                const int c = ks * 16 + col_off;
#pragma unroll
                for (int ntp = 0; ntp < 4; ntp++) {
                    uint32_t kf[4];
                    ldsm4(kt_u + (uint32_t)((ntp * 16 + row_off) * AKPH + c) * 2, kf);
                    uint32_t b0[2] = {kf[0], kf[1]};
                    uint32_t b1[2] = {kf[2], kf[3]};
                    mma16n8k16(s[2 * ntp],     qf[ks], b0);
                    mma16n8k16(s[2 * ntp + 1], qf[ks], b1);
                }
            }
        }

        // ---- scale + mask ----
        const bool need_mask = (kt == qi) || (((kt + 1) << 6) > len);
        if (need_mask) {
            const int qg0 = qi * 64 + warp * 16 + lq;
#pragma unroll
            for (int nt = 0; nt < 8; nt++) {
#pragma unroll
                for (int j = 0; j < 4; j++) {
                    float v = s[nt][j] * SE;
                    const int kg = kt * 64 + nt * 8 + (lr << 1) + (j & 1);
                    const int qg = qg0 + ((j & 2) << 2);
                    if (kg > qg || kg >= len) v = -1e30f;
                    s[nt][j] = v;
                }
            }
        } else {
#pragma unroll
            for (int nt = 0; nt < 8; nt++)
#pragma unroll
                for (int j = 0; j < 4; j++) s[nt][j] *= SE;
        }

        // ---- online softmax: max reduce, f16x2 exp, store P ----
        {
            float tA = -1e30f, tB = -1e30f;
#pragma unroll
            for (int nt = 0; nt < 8; nt++) {
                tA = fmaxf(tA, fmaxf(s[nt][0], s[nt][1]));
                tB = fmaxf(tB, fmaxf(s[nt][2], s[nt][3]));
            }
            tA = fmaxf(tA, __shfl_xor_sync(0xffffffffu, tA, 1));
            tA = fmaxf(tA, __shfl_xor_sync(0xffffffffu, tA, 2));
            tB = fmaxf(tB, __shfl_xor_sync(0xffffffffu, tB, 1));
            tB = fmaxf(tB, __shfl_xor_sync(0xffffffffu, tB, 2));
            const float mA = fmaxf(mrowA, tA), mB = fmaxf(mrowB, tB);
            const float aA = exp2_(mrowA - mA), aB = exp2_(mrowB - mB);

#pragma unroll
            for (int nt = 0; nt < 8; nt++) {
                const uint32_t x0 = packh2(s[nt][0] - mA, s[nt][1] - mA);
                const uint32_t x1 = packh2(s[nt][2] - mB, s[nt][3] - mB);
                const int c = nt * 8 + (lr << 1);
                *reinterpret_cast<uint32_t*>(&Ps[prow * AKPH + c]) = ex2h2(x0);
                *reinterpret_cast<uint32_t*>(&Ps[(prow + 8) * AKPH + c]) = ex2h2(x1);
            }
            mrowA = mA;
            mrowB = mB;
            lacc[0] *= aA; lacc[1] *= aA;
            lacc[2] *= aB; lacc[3] *= aB;
#pragma unroll
            for (int nt = 0; nt < 8; nt++) {
                oacc[nt][0] *= aA; oacc[nt][1] *= aA;
                oacc[nt][2] *= aB; oacc[nt][3] *= aB;
            }
        }
        __syncwarp();

        // ---- O += P V ; l += P @ ones ----
        {
            const int prow_off = warp * 16 + (sub & 1) * 8 + l7;
            const int pcol_off = (sub >> 1) * 8;
#pragma unroll
            for (int ks = 0; ks < 4; ks++) {
                uint32_t pa[4];
                ldsm4(ps_u + (uint32_t)(prow_off * AKPH + ks * 16 + pcol_off) * 2, pa);
                mma16n8k16(lacc, pa, ones2);
#pragma unroll
                for (int ntp = 0; ntp < 4; ntp++) {
                    const int row = ks * 16 + ((lane >> 3) & 1) * 8 + (lane & 7);
                    const int col = ntp * 16 + ((lane >> 4) << 3);
                    uint32_t vf[4];
                    ldsm4t(vt_u + (uint32_t)(row * AKPH + col) * 2, vf);
                    uint32_t b0[2] = {vf[0], vf[1]}, b1[2] = {vf[2], vf[3]};
                    mma16n8k16(oacc[2 * ntp],     pa, b0);
                    mma16n8k16(oacc[2 * ntp + 1], pa, b1);
                }
            }
        }
        __syncwarp();
    }

    // ---- finalize: fp16 O in [b,t,h*64+dh] ----
    __half* __restrict__ Ob = g_O + ((size_t)b * TT) * DD + h * DHH;
    {
        const float invA = 1.f / lacc[0], invB = 1.f / lacc[2];
        const int q0 = qi * 64 + warp * 16 + lq;
#pragma unroll
        for (int nt = 0; nt < 8; nt++) {
            const int dh = nt * 8 + (lr << 1);
            *reinterpret_cast<uint32_t*>(&Ob[(size_t)q0 * DD + dh]) =
                packh2(oacc[nt][0] * invA, oacc[nt][1] * invA);
            *reinterpret_cast<uint32_t*>(&Ob[(size_t)(q0 + 8) * DD + dh]) =
                packh2(oacc[nt][2] * invB, oacc[nt][3] * invB);
        }
    }
}

// ---------------------------------------------------------------------------
// Launch
// ---------------------------------------------------------------------------
extern "C" void kernel_launch(void* const* d_in, const int* in_sizes, int n_in,
                              void* d_out, int out_size)
{
    const float* big[4] = {nullptr, nullptr, nullptr, nullptr};
    const float* w[4]   = {nullptr, nullptr, nullptr, nullptr};
    const unsigned char* kpm = nullptr;
    int nbig = 0, nw = 0;
    for (int i = 0; i < n_in; i++) {
        if (in_sizes[i] == TT * TT && nbig < 4) big[nbig++] = (const float*)d_in[i];
        else if (in_sizes[i] == DD * DD && nw < 4) w[nw++] = (const float*)d_in[i];
        else if (in_sizes[i] == BB * TT) kpm = (const unsigned char*)d_in[i];
    }
    const float* query = big[0];
    const float* key_t = big[1];
    const float* value = big[2];
    const float* Wq = w[0];
    const float* Wk = w[1];
    const float* Wv = w[2];
    const float* Wo = w[3];
    float* out = (float*)d_out;

    static bool attr_set = false;
    if (!attr_set) {
        cudaFuncSetAttribute(proj_qkv_kernel, cudaFuncAttributeMaxDynamicSharedMemorySize, PSMEM_QKV);
        cudaFuncSetAttribute(proj_o_kernel, cudaFuncAttributeMaxDynamicSharedMemorySize, PSMEM_O);
        cudaFuncSetAttribute(attn_kernel, cudaFuncAttributeMaxDynamicSharedMemorySize, A_SMEM);
        attr_set = true;
    }

    lens_kernel<<<BB, 256>>>(kpm);
    round_kernel<<<dim3((DD * DD) / 4 / 256, 4), 256>>>(Wq, Wk, Wv, Wo);
    proj_qkv_kernel<<<dim3(DD / PBN, MM / PBM, 3), 128, PSMEM_QKV>>>(query, key_t, value);
    attn_kernel<<<dim3(TT / 64, HH, BB), 128, A_SMEM>>>();
    proj_o_kernel<<<dim3(DD / PBN, MM / PBM, 1), 128, PSMEM_O>>>(out);
}